// round 16
// baseline (speedup 1.0000x reference)
#include <cuda_runtime.h>
#include <math.h>

// ---------------- problem constants ----------------
#define NLEV   16
#define TBL    524288u          // T = 2^19 entries per level
#define TMASK  (TBL - 1u)
#define HP1    2654435761u
#define HP2    805459861u

// static dense/hash split: dense <=> (res+1)^3 <= T <=> res <= 79.
// level resolutions near the cutoff are 59 (l=4) and 81 (l=5) -> robust.
#define NDENSE 5

typedef unsigned long long ull;

// MLP weights in constant memory (warp-uniform -> LDC, keeps LSU free)
__constant__ __align__(16) float cW1[32 * 64];
__constant__ __align__(16) float cW2[64 * 16];

struct LevelParams {
    float    resf[NLEV];   // (float)res[l]   (host double-exact)
    unsigned s[NLEV];      // res[l] + 1      (dense stride)
};

// ---------------- packed f32x2 helpers ----------------
__device__ __forceinline__ ull pack2(float v) {
    ull r; unsigned u = __float_as_uint(v);
    asm("mov.b64 %0, {%1,%1};" : "=l"(r) : "r"(u));
    return r;
}
__device__ __forceinline__ ull fma2(ull a, ull b, ull c) {
    ull d;
    asm("fma.rn.f32x2 %0, %1, %2, %3;" : "=l"(d) : "l"(a), "l"(b), "l"(c));
    return d;
}
__device__ __forceinline__ float2 unpack2(ull v) {
    unsigned lo, hi;
    asm("mov.b64 {%0,%1}, %2;" : "=r"(lo), "=r"(hi) : "l"(v));
    return make_float2(__uint_as_float(lo), __uint_as_float(hi));
}

// Dual-path paired gather, alignment-safe; (lo,hi) of the aligned 16B block
// when adjacent, caller swaps WEIGHTS by parity (champion-proven numerics).
__device__ __forceinline__ void gather_pair_raw(const float2* __restrict__ tab,
                                                unsigned a0, unsigned a1,
                                                unsigned adj,
                                                float& lox, float& loy,
                                                float& hix, float& hiy) {
    const float4* pa = reinterpret_cast<const float4*>(tab + (a0 & ~1u));
    asm volatile("{\n\t"
                 ".reg .pred p;\n\t"
                 "setp.ne.u32 p, %4, 0;\n\t"
                 "@p  ld.global.nc.v4.f32 {%0,%1,%2,%3}, [%5];\n\t"
                 "@!p ld.global.nc.v2.f32 {%0,%1}, [%6];\n\t"
                 "@!p ld.global.nc.v2.f32 {%2,%3}, [%7];\n\t"
                 "}"
                 : "=f"(lox), "=f"(loy), "=f"(hix), "=f"(hiy)
                 : "r"(adj), "l"(pa), "l"(tab + a0), "l"(tab + a1));
}

__device__ __forceinline__ float clip01(float v) {
    return fminf(fmaxf((v + 1.0f) * 0.5f, 0.0f), 1.0f);
}

// One level's trilinear encode. DENSE is compile-time: no runtime branch,
// only one index-computation body per unrolled level.
template <bool DENSE>
__device__ __forceinline__ void level_encode(const float2* __restrict__ tab,
                                             unsigned s, float rf,
                                             float x01, float y01, float z01,
                                             float& eo0, float& eo1)
{
    float px = x01 * rf, py = y01 * rf, pz = z01 * rf;
    float fpx = floorf(px), fpy = floorf(py), fpz = floorf(pz);
    float fx = px - fpx, fy = py - fpy, fz = pz - fpz;
    unsigned ix = (unsigned)fpx, iy = (unsigned)fpy, iz = (unsigned)fpz;
    float wx0 = 1.0f - fx, wy0 = 1.0f - fy, wz0 = 1.0f - fz;

    unsigned i0a[4], i1a[4];
    float    wyz[4];
    if (DENSE) {
#pragma unroll
        for (int k = 0; k < 2; k++) {
#pragma unroll
            for (int j = 0; j < 2; j++) {
                unsigned a = s * ((iy + (unsigned)j) + s * (iz + (unsigned)k));
                int c = k * 2 + j;
                i0a[c] = ix + a;
                i1a[c] = ix + 1u + a;
                wyz[c] = (j ? fy : wy0) * (k ? fz : wz0);
            }
        }
    } else {
        unsigned hy0 = iy * HP1;
        unsigned hz0 = iz * HP2;
#pragma unroll
        for (int k = 0; k < 2; k++) {
#pragma unroll
            for (int j = 0; j < 2; j++) {
                unsigned a = (hy0 + (j ? HP1 : 0u)) ^ (hz0 + (k ? HP2 : 0u));
                int c = k * 2 + j;
                i0a[c] = (ix ^ a) & TMASK;
                i1a[c] = ((ix + 1u) ^ a) & TMASK;
                wyz[c] = (j ? fy : wy0) * (k ? fz : wz0);
            }
        }
    }

    float lox[4], loy[4], hix[4], hiy[4];
    unsigned adj[4];
#pragma unroll
    for (int c = 0; c < 4; c++) {
        adj[c] = ((i0a[c] ^ i1a[c]) == 1u) ? 1u : 0u;
        gather_pair_raw(tab, i0a[c], i1a[c], adj[c],
                        lox[c], loy[c], hix[c], hiy[c]);
    }

    float e0 = 0.0f, e1 = 0.0f;
#pragma unroll
    for (int c = 0; c < 4; c++) {
        bool swp = (adj[c] != 0u) && ((i0a[c] & 1u) != 0u);
        float w0 = wx0 * wyz[c];
        float w1 = fx  * wyz[c];
        float wlo = swp ? w1 : w0;
        float whi = swp ? w0 : w1;
        e0 = fmaf(wlo, lox[c], fmaf(whi, hix[c], e0));
        e1 = fmaf(wlo, loy[c], fmaf(whi, hiy[c], e1));
    }
    eo0 = e0;
    eo1 = e1;
}

// ---------------- fused kernel: hashgrid encode + MLP ----------------
#define BLK 256

__global__ void __launch_bounds__(BLK, 3)
hashgrid_mlp_kernel(const float* __restrict__ xyzs,
                    const float* __restrict__ tables,
                    float* __restrict__ out,
                    int N, LevelParams lp)
{
    // One 32KB buffer: phase 1 = senc[16][BLK] float2 (private columns),
    //                  phase 2 = sgeo[BLK*15] float (coalesced geo staging)
    __shared__ __align__(16) char sbuf[NLEV * BLK * 8];
    float2* senc = reinterpret_cast<float2*>(sbuf);
    float*  sgeo = reinterpret_cast<float*>(sbuf);

    int pid = blockIdx.x * BLK + threadIdx.x;
    bool active = (pid < N);
    unsigned tid = threadIdx.x;

    float o[16];

    if (active) {
        float x = xyzs[3 * pid + 0];
        float y = xyzs[3 * pid + 1];
        float z = xyzs[3 * pid + 2];
        float x01 = clip01(x), y01 = clip01(y), z01 = clip01(z);

        const float2* __restrict__ gtab =
            reinterpret_cast<const float2*>(tables);

        // gather phase: enc -> smem (full unroll, compile-time dense split)
#pragma unroll
        for (int l = 0; l < NDENSE; l++) {
            float e0, e1;
            level_encode<true>(gtab + (size_t)l * TBL, lp.s[l], lp.resf[l],
                               x01, y01, z01, e0, e1);
            senc[l * BLK + tid] = make_float2(e0, e1);
        }
#pragma unroll
        for (int l = NDENSE; l < NLEV; l++) {
            float e0, e1;
            level_encode<false>(gtab + (size_t)l * TBL, lp.s[l], lp.resf[l],
                                x01, y01, z01, e0, e1);
            senc[l * BLK + tid] = make_float2(e0, e1);
        }

        // ---------------- MLP: two 32-wide hidden chunks ----------------
        ull op[8];
#pragma unroll
        for (int j = 0; j < 8; j++) op[j] = 0ull;

#pragma unroll
        for (int half = 0; half < 2; half++) {
            ull hp[16];
#pragma unroll
            for (int j = 0; j < 16; j++) hp[j] = 0ull;

#pragma unroll
            for (int ip = 0; ip < 16; ip++) {
                float2 e = senc[ip * BLK + tid];
                ull e0 = pack2(e.x), e1 = pack2(e.y);
                const ulonglong2* r0 = reinterpret_cast<const ulonglong2*>(
                    cW1 + (2 * ip) * 64 + 32 * half);
                const ulonglong2* r1 = reinterpret_cast<const ulonglong2*>(
                    cW1 + (2 * ip + 1) * 64 + 32 * half);
#pragma unroll
                for (int j = 0; j < 8; j++) {
                    ulonglong2 wa = r0[j];
                    ulonglong2 wb = r1[j];
                    hp[2 * j]     = fma2(e0, wa.x, hp[2 * j]);
                    hp[2 * j + 1] = fma2(e0, wa.y, hp[2 * j + 1]);
                    hp[2 * j]     = fma2(e1, wb.x, hp[2 * j]);
                    hp[2 * j + 1] = fma2(e1, wb.y, hp[2 * j + 1]);
                }
            }

            // relu + layer-2 accumulation, consuming hp immediately
#pragma unroll
            for (int j = 0; j < 16; j++) {
                float2 p = unpack2(hp[j]);
                ull eh0 = pack2(fmaxf(p.x, 0.0f));
                ull eh1 = pack2(fmaxf(p.y, 0.0f));
                int i2 = 32 * half + 2 * j;
                const ulonglong2* w0 =
                    reinterpret_cast<const ulonglong2*>(cW2 + i2 * 16);
                const ulonglong2* w1 = w0 + 4;
#pragma unroll
                for (int q = 0; q < 4; q++) {
                    ulonglong2 a = w0[q];
                    ulonglong2 b = w1[q];
                    op[2 * q]     = fma2(eh0, a.x, op[2 * q]);
                    op[2 * q + 1] = fma2(eh0, a.y, op[2 * q + 1]);
                    op[2 * q]     = fma2(eh1, b.x, op[2 * q]);
                    op[2 * q + 1] = fma2(eh1, b.y, op[2 * q + 1]);
                }
            }
        }

#pragma unroll
        for (int j = 0; j < 8; j++) {
            float2 p = unpack2(op[j]);
            o[2 * j]     = p.x;
            o[2 * j + 1] = p.y;
        }

        out[pid] = __expf(o[0]);        // coalesced sigma store (MUFU path)
    }

    __syncthreads();                     // senc dead -> reuse buffer for geo

    if (active) {
#pragma unroll
        for (int k = 0; k < 15; k++)
            sgeo[tid * 15 + k] = o[k + 1];
    }
    __syncthreads();

    // cooperative coalesced store of this block's geo region
    int base = blockIdx.x * BLK;
    int nPts = min(BLK, N - base);
    if (nPts <= 0) return;
    float* gbase = out + (size_t)N + (size_t)base * 15;
    int total = nPts * 15;
    if (nPts == BLK && ((((size_t)gbase) & 15u) == 0)) {
        float4* g4 = reinterpret_cast<float4*>(gbase);
        const float4* s4 = reinterpret_cast<const float4*>(sgeo);
        int n4 = total / 4;  // 960
        for (int t = tid; t < n4; t += BLK) g4[t] = s4[t];
    } else {
        for (int t = tid; t < total; t += BLK) gbase[t] = sgeo[t];
    }
}

// ---------------- host ----------------
static LevelParams make_level_params()
{
    LevelParams lp;
    double pls = exp(log(2048.0 / 16.0) / (double)(NLEV - 1));
    for (int l = 0; l < NLEV; l++) {
        int r = (int)ceil(16.0 * pow(pls, (double)l));
        lp.resf[l]  = (float)r;
        lp.s[l]     = (unsigned)(r + 1);
    }
    return lp;
}

extern "C" void kernel_launch(void* const* d_in, const int* in_sizes, int n_in,
                              void* d_out, int out_size)
{
    (void)n_in; (void)out_size;
    const float* xyzs   = (const float*)d_in[0];
    const float* tables = (const float*)d_in[1];
    int N = in_sizes[0] / 3;

    cudaMemcpyToSymbolAsync(cW1, d_in[2], 32 * 64 * sizeof(float), 0,
                            cudaMemcpyDeviceToDevice, 0);
    cudaMemcpyToSymbolAsync(cW2, d_in[3], 64 * 16 * sizeof(float), 0,
                            cudaMemcpyDeviceToDevice, 0);

    LevelParams lp = make_level_params();

    int gridN = (N + BLK - 1) / BLK;
    hashgrid_mlp_kernel<<<gridN, BLK>>>(xyzs, tables, (float*)d_out, N, lp);
}

// round 17
// speedup vs baseline: 3.2778x; 3.2778x over previous
#include <cuda_runtime.h>
#include <math.h>

// ---------------- problem constants ----------------
#define NLEV   16
#define TBL    524288u          // T = 2^19 entries per level
#define TMASK  (TBL - 1u)
#define HP1    2654435761u
#define HP2    805459861u

typedef unsigned long long ull;

// MLP weights in constant memory (warp-uniform -> LDC, keeps LSU free)
__constant__ __align__(16) float cW1[32 * 64];
__constant__ __align__(16) float cW2[64 * 16];

struct LevelParams {
    float    resf[NLEV];   // (float)res[l]
    unsigned s[NLEV];      // res[l] + 1  (dense stride)
    unsigned dense[NLEV];  // (res+1)^3 <= T ?
};

// ---------------- packed f32x2 helpers ----------------
__device__ __forceinline__ ull pack2(float v) {
    ull r; unsigned u = __float_as_uint(v);
    asm("mov.b64 %0, {%1,%1};" : "=l"(r) : "r"(u));
    return r;
}
__device__ __forceinline__ ull fma2(ull a, ull b, ull c) {
    ull d;
    asm("fma.rn.f32x2 %0, %1, %2, %3;" : "=l"(d) : "l"(a), "l"(b), "l"(c));
    return d;
}
__device__ __forceinline__ float2 unpack2(ull v) {
    unsigned lo, hi;
    asm("mov.b64 {%0,%1}, %2;" : "=r"(lo), "=r"(hi) : "l"(v));
    return make_float2(__uint_as_float(lo), __uint_as_float(hi));
}

// Dual-path paired gather, alignment-safe. Returns the aligned 16B block's
// two entries in (lo, hi) order when adjacent; caller swaps WEIGHTS by
// parity of a0 (2 SELs/pair instead of 8).
// adj != 0 ((a0^a1)==1): one LDG.128 at (a0 & ~1) covers both entries.
// adj == 0: two LDG.64 into (lo, hi) = (entry a0, entry a1); weight-swap
// is disabled by construction in that case.
__device__ __forceinline__ void gather_pair_raw(const float2* __restrict__ tab,
                                                unsigned a0, unsigned a1,
                                                unsigned adj,
                                                float& lox, float& loy,
                                                float& hix, float& hiy) {
    const float4* pa = reinterpret_cast<const float4*>(tab + (a0 & ~1u));
    asm volatile("{\n\t"
                 ".reg .pred p;\n\t"
                 "setp.ne.u32 p, %4, 0;\n\t"
                 "@p  ld.global.nc.v4.f32 {%0,%1,%2,%3}, [%5];\n\t"
                 "@!p ld.global.nc.v2.f32 {%0,%1}, [%6];\n\t"
                 "@!p ld.global.nc.v2.f32 {%2,%3}, [%7];\n\t"
                 "}"
                 : "=f"(lox), "=f"(loy), "=f"(hix), "=f"(hiy)
                 : "r"(adj), "l"(pa), "l"(tab + a0), "l"(tab + a1));
}

__device__ __forceinline__ float clip01(float v) {
    return fminf(fmaxf((v + 1.0f) * 0.5f, 0.0f), 1.0f);
}

// ---------------- fused kernel: hashgrid encode + MLP (champion) -----------
// NOTE: the per-level runtime dense/hash branch is LOAD-BEARING: removing it
// (compile-time template split, R14/R16) lets ptxas front-batch all levels'
// gathers, which deterministically collapses L2 table residency
// (DRAM 3.9% -> 39.2%) and runs 3.3x slower. Do not "optimize" it away.
#define BLK 256

__global__ void __launch_bounds__(BLK, 3)
hashgrid_mlp_kernel(const float* __restrict__ xyzs,
                    const float* __restrict__ tables,
                    float* __restrict__ out,
                    int N, LevelParams lp)
{
    // One 32KB buffer, used as:
    //   phase 1: senc[16][BLK] float2  (per-thread private column -> no sync)
    //   phase 2: sgeo[BLK*15] float    (coalesced geo staging)
    __shared__ __align__(16) char sbuf[NLEV * BLK * 8];
    float2* senc = reinterpret_cast<float2*>(sbuf);
    float*  sgeo = reinterpret_cast<float*>(sbuf);

    int pid = blockIdx.x * BLK + threadIdx.x;
    bool active = (pid < N);
    unsigned tid = threadIdx.x;

    float o[16];

    if (active) {
        float x = xyzs[3 * pid + 0];
        float y = xyzs[3 * pid + 1];
        float z = xyzs[3 * pid + 2];
        float x01 = clip01(x), y01 = clip01(y), z01 = clip01(z);

        // ---------------- gather phase: enc -> smem (full unroll) ----------
#pragma unroll
        for (int l = 0; l < NLEV; l++) {
            const float2* __restrict__ tab =
                reinterpret_cast<const float2*>(tables) + (size_t)l * TBL;

            float rf = lp.resf[l];
            float px = x01 * rf, py = y01 * rf, pz = z01 * rf;
            float fpx = floorf(px), fpy = floorf(py), fpz = floorf(pz);
            float fx = px - fpx, fy = py - fpy, fz = pz - fpz;
            unsigned ix = (unsigned)fpx, iy = (unsigned)fpy, iz = (unsigned)fpz;
            float wx0 = 1.0f - fx, wy0 = 1.0f - fy, wz0 = 1.0f - fz;

            unsigned i0a[4], i1a[4];
            float    wyz[4];
            if (lp.dense[l]) {
                unsigned s = lp.s[l];
#pragma unroll
                for (int k = 0; k < 2; k++) {
#pragma unroll
                    for (int j = 0; j < 2; j++) {
                        unsigned a = s * ((iy + (unsigned)j) + s * (iz + (unsigned)k));
                        int c = k * 2 + j;
                        i0a[c] = ix + a;
                        i1a[c] = ix + 1u + a;
                        wyz[c] = (j ? fy : wy0) * (k ? fz : wz0);
                    }
                }
            } else {
                unsigned hy0 = iy * HP1;
                unsigned hz0 = iz * HP2;
#pragma unroll
                for (int k = 0; k < 2; k++) {
#pragma unroll
                    for (int j = 0; j < 2; j++) {
                        unsigned a = (hy0 + (j ? HP1 : 0u)) ^ (hz0 + (k ? HP2 : 0u));
                        int c = k * 2 + j;
                        i0a[c] = (ix ^ a) & TMASK;
                        i1a[c] = ((ix + 1u) ^ a) & TMASK;
                        wyz[c] = (j ? fy : wy0) * (k ? fz : wz0);
                    }
                }
            }

            float lox[4], loy[4], hix[4], hiy[4];
            unsigned adj[4];
#pragma unroll
            for (int c = 0; c < 4; c++) {
                adj[c] = ((i0a[c] ^ i1a[c]) == 1u) ? 1u : 0u;
                gather_pair_raw(tab, i0a[c], i1a[c], adj[c],
                                lox[c], loy[c], hix[c], hiy[c]);
            }

            float e0 = 0.0f, e1 = 0.0f;
#pragma unroll
            for (int c = 0; c < 4; c++) {
                // weight-swap: when adj && (a0 odd), entry a0 is the HI half
                bool swp = (adj[c] != 0u) && ((i0a[c] & 1u) != 0u);
                float w0 = wx0 * wyz[c];
                float w1 = fx  * wyz[c];
                float wlo = swp ? w1 : w0;
                float whi = swp ? w0 : w1;
                e0 = fmaf(wlo, lox[c], fmaf(whi, hix[c], e0));
                e1 = fmaf(wlo, loy[c], fmaf(whi, hiy[c], e1));
            }
            senc[l * BLK + tid] = make_float2(e0, e1);
        }

        // ---------------- MLP: two 32-wide hidden chunks ----------------
        ull op[8];
#pragma unroll
        for (int j = 0; j < 8; j++) op[j] = 0ull;

#pragma unroll
        for (int half = 0; half < 2; half++) {
            ull hp[16];
#pragma unroll
            for (int j = 0; j < 16; j++) hp[j] = 0ull;

#pragma unroll
            for (int ip = 0; ip < 16; ip++) {
                float2 e = senc[ip * BLK + tid];
                ull e0 = pack2(e.x), e1 = pack2(e.y);
                const ulonglong2* r0 = reinterpret_cast<const ulonglong2*>(
                    cW1 + (2 * ip) * 64 + 32 * half);
                const ulonglong2* r1 = reinterpret_cast<const ulonglong2*>(
                    cW1 + (2 * ip + 1) * 64 + 32 * half);
#pragma unroll
                for (int j = 0; j < 8; j++) {
                    ulonglong2 wa = r0[j];
                    ulonglong2 wb = r1[j];
                    hp[2 * j]     = fma2(e0, wa.x, hp[2 * j]);
                    hp[2 * j + 1] = fma2(e0, wa.y, hp[2 * j + 1]);
                    hp[2 * j]     = fma2(e1, wb.x, hp[2 * j]);
                    hp[2 * j + 1] = fma2(e1, wb.y, hp[2 * j + 1]);
                }
            }

            // relu + layer-2 accumulation, consuming hp immediately
#pragma unroll
            for (int j = 0; j < 16; j++) {
                float2 p = unpack2(hp[j]);
                ull eh0 = pack2(fmaxf(p.x, 0.0f));
                ull eh1 = pack2(fmaxf(p.y, 0.0f));
                int i2 = 32 * half + 2 * j;
                const ulonglong2* w0 =
                    reinterpret_cast<const ulonglong2*>(cW2 + i2 * 16);
                const ulonglong2* w1 = w0 + 4;
#pragma unroll
                for (int q = 0; q < 4; q++) {
                    ulonglong2 a = w0[q];
                    ulonglong2 b = w1[q];
                    op[2 * q]     = fma2(eh0, a.x, op[2 * q]);
                    op[2 * q + 1] = fma2(eh0, a.y, op[2 * q + 1]);
                    op[2 * q]     = fma2(eh1, b.x, op[2 * q]);
                    op[2 * q + 1] = fma2(eh1, b.y, op[2 * q + 1]);
                }
            }
        }

#pragma unroll
        for (int j = 0; j < 8; j++) {
            float2 p = unpack2(op[j]);
            o[2 * j]     = p.x;
            o[2 * j + 1] = p.y;
        }

        out[pid] = __expf(o[0]);        // coalesced sigma store (MUFU path)
    }

    __syncthreads();                     // senc dead -> reuse buffer for geo

    if (active) {
#pragma unroll
        for (int k = 0; k < 15; k++)
            sgeo[tid * 15 + k] = o[k + 1];
    }
    __syncthreads();

    // cooperative coalesced store of this block's geo region
    int base = blockIdx.x * BLK;
    int nPts = min(BLK, N - base);
    if (nPts <= 0) return;
    float* gbase = out + (size_t)N + (size_t)base * 15;
    int total = nPts * 15;
    if (nPts == BLK && ((((size_t)gbase) & 15u) == 0)) {
        float4* g4 = reinterpret_cast<float4*>(gbase);
        const float4* s4 = reinterpret_cast<const float4*>(sgeo);
        int n4 = total / 4;  // 960
        for (int t = tid; t < n4; t += BLK) g4[t] = s4[t];
    } else {
        for (int t = tid; t < total; t += BLK) gbase[t] = sgeo[t];
    }
}

// ---------------- host ----------------
static LevelParams make_level_params()
{
    LevelParams lp;
    double pls = exp(log(2048.0 / 16.0) / (double)(NLEV - 1));
    for (int l = 0; l < NLEV; l++) {
        int r = (int)ceil(16.0 * pow(pls, (double)l));
        lp.resf[l]  = (float)r;
        lp.s[l]     = (unsigned)(r + 1);
        long long s = (long long)(r + 1);
        lp.dense[l] = (s * s * s <= (long long)TBL) ? 1u : 0u;
    }
    return lp;
}

extern "C" void kernel_launch(void* const* d_in, const int* in_sizes, int n_in,
                              void* d_out, int out_size)
{
    (void)n_in; (void)out_size;
    const float* xyzs   = (const float*)d_in[0];
    const float* tables = (const float*)d_in[1];
    int N = in_sizes[0] / 3;

    cudaMemcpyToSymbolAsync(cW1, d_in[2], 32 * 64 * sizeof(float), 0,
                            cudaMemcpyDeviceToDevice, 0);
    cudaMemcpyToSymbolAsync(cW2, d_in[3], 64 * 16 * sizeof(float), 0,
                            cudaMemcpyDeviceToDevice, 0);

    LevelParams lp = make_level_params();

    int gridN = (N + BLK - 1) / BLK;
    hashgrid_mlp_kernel<<<gridN, BLK>>>(xyzs, tables, (float*)d_out, N, lp);
}